// round 11
// baseline (speedup 1.0000x reference)
#include <cuda_runtime.h>
#include <math.h>

// Problem constants
#define BATCH 16
#define LROWS 192   // 6*L rows of raw
#define AC    2046  // attributor columns
#define MC    2048  // M = A + 2
#define LD    32    // L
#define TCOL  128   // columns per block tile
#define NCB   16    // col-blocks: 16*128 = 2048 slots (2046 cols + 2 specials)
#define NSTG  24    // 24 stages x 8 rows = 192 rows
#define RING  4

// Scratch (device globals; no allocation allowed)
__device__ float g_wq[BATCH][2][64];
__device__ float g_wk[BATCH][2][64];
__device__ float g_A[2][MC];
__device__ float g_P[2][MC];
__device__ float g_R[2][MC];

__device__ __forceinline__ unsigned smem_u32(const void* p) {
    unsigned a;
    asm("{ .reg .u64 t; cvta.to.shared.u64 t, %1; cvt.u32.u64 %0, t; }"
        : "=r"(a) : "l"(p));
    return a;
}
__device__ __forceinline__ void cp8(unsigned dst, const float* src, unsigned sz) {
    asm volatile("cp.async.ca.shared.global [%0], [%1], 8, %2;"
                 :: "r"(dst), "l"(src), "r"(sz));
}
__device__ __forceinline__ void cpcommit() {
    asm volatile("cp.async.commit_group;" ::: "memory");
}
__device__ __forceinline__ void cpwait(int k) {
    if (k <= 0)      asm volatile("cp.async.wait_group 0;" ::: "memory");
    else if (k == 1) asm volatile("cp.async.wait_group 1;" ::: "memory");
    else if (k == 2) asm volatile("cp.async.wait_group 2;" ::: "memory");
    else             asm volatile("cp.async.wait_group 3;" ::: "memory");
}

// ---------------------------------------------------------------------------
// Kernel 1 (prep): wq/wk folds + adj/iw packing + d_out zeroing. (unchanged)
// ---------------------------------------------------------------------------
__global__ __launch_bounds__(128) void prep_kernel(
    const float* __restrict__ user, const float* __restrict__ item,
    const float* __restrict__ W2,
    const float* __restrict__ adj, const float* __restrict__ iw,
    float* __restrict__ out) {

    int blk = blockIdx.x;
    int t = threadIdx.x;

    if (blk < 32) {
        int b = blk >> 1;
        int n = blk & 1;
        const float* src = (n ? item : user) + b * LROWS;
        __shared__ float W2s[128 * 33];
        __shared__ float xr[128];
        __shared__ float qs[32];
        __shared__ float ks[32];

        xr[t] = fmaxf(src[t], 0.0f);
        #pragma unroll
        for (int i = 0; i < 32; i++) {
            int idx = t + i * 128;
            W2s[(idx >> 5) * 33 + (idx & 31)] = W2[idx];
        }
        __syncthreads();

        if (t < 32) {
            float s = 0.0f;
            #pragma unroll
            for (int j = 0; j < 64; j++) s = fmaf(xr[j], W2s[j * 33 + t], s);
            qs[t] = s;
        } else if (t < 64) {
            int l = t - 32;
            float s = 0.0f;
            #pragma unroll
            for (int j = 0; j < 64; j++) s = fmaf(xr[64 + j], W2s[(64 + j) * 33 + l], s);
            ks[l] = s;
        }
        __syncthreads();
        if (t < 64) {
            float swq = 0.0f, swk = 0.0f;
            #pragma unroll
            for (int l = 0; l < 32; l++) {
                swq = fmaf(W2s[t * 33 + l],        ks[l], swq);
                swk = fmaf(W2s[(64 + t) * 33 + l], qs[l], swk);
            }
            g_wq[b][n][t] = swq;
            g_wk[b][n][t] = swk;
        }
    } else {
        if (blk == 32) {
            float4 z = make_float4(0.f, 0.f, 0.f, 0.f);
            ((float4*)out)[t]       = z;
            ((float4*)out)[t + 128] = z;
        }
        int m = (blk - 32) * 128 + t;
        size_t row = (size_t)m * MC;
        float a0 = adj[row];
        float a1 = adj[row + (MC - 1)];
        g_A[0][m] = a0;
        g_A[1][m] = a1;
        g_P[0][m] = a0 * iw[row];
        g_P[1][m] = a1 * iw[row + (MC - 1)];
        g_R[0][m] = adj[m] * iw[m];
        size_t lastrow = (size_t)(MC - 1) * MC + m;
        g_R[1][m] = adj[lastrow] * iw[lastrow];
    }
}

// ---------------------------------------------------------------------------
// Kernel 2 (main): cp.async-pipelined streaming.
// grid (cb=16, b=16) = 256 blocks x 512 threads.
// Thread (p = t>>7, c = t&127): p owns rows {2p, 2p+1} of each 8-row stage,
// c is the column slot. cp.async chunk map: row = t>>6, col-pair = t&63,
// dst offset = 8*t within the stage buffer.
// Stages 0-7: Q rows; 8-15: K rows (h accumulation in regs);
// stage-16 boundary: causal; 16-23: V rows folded into S via shfl butterfly.
// ---------------------------------------------------------------------------
__global__ __launch_bounds__(512, 2) void main_kernel(
    const float* __restrict__ user, const float* __restrict__ item,
    const float* __restrict__ attributor, const float* __restrict__ W1,
    const float* __restrict__ W2, float* __restrict__ out) {

    __shared__ __align__(16) float pool[11904];   // 47.6 KB
    float*  ring_a = pool;                    // 4 x 1024 floats (16 KB)
    float*  ring_w = pool + 4096;             // 4 x 1024 floats (16 KB)
    float4* hqk    = (float4*)(pool + 8192);  // [p*128+c] (8 KB)
    float*  Spart  = pool + 8192;             // alias over hqk (2 KB; used after)
    float*  c_sh   = pool + 10240;            // [n*128+c]
    float*  aA     = pool + 10496;            // [n*128+c]
    float*  aP     = pool + 10752;
    float*  aR     = pool + 11008;
    float*  us     = pool + 11264;            // user rows (last block only)
    float*  it     = pool + 11456;            // item rows
    float*  wq     = pool + 11648;            // [n*64+j]
    float*  wk     = pool + 11776;

    int b  = blockIdx.y;
    int cb = blockIdx.x;
    int t  = threadIdx.x;
    int p  = t >> 7;              // 0..3
    int c  = t & 127;             // column slot
    int c0 = cb * TCOL;
    bool lastcb  = (cb == NCB - 1);
    bool special = lastcb && (c >= 126);   // c=126 -> node 0 (user), c=127 -> node 2047 (item)

    // cp.async thread-constant addressing
    int krow = t >> 6;            // row-in-stage 0..7
    int kcol = t & 63;            // 8B chunk (cols 2k, 2k+1)
    const float* srcA = attributor + (size_t)(b * LROWS + krow) * AC + c0 + 2 * kcol;
    const float* srcW = W1 + (size_t)krow * AC + c0 + 2 * kcol;
    unsigned dstA = smem_u32(ring_a) + 8u * t;
    unsigned dstW = smem_u32(ring_w) + 8u * t;
    unsigned csz  = (lastcb && kcol == 63) ? 0u : 8u;   // zero-fill special slots
    const size_t sstep = (size_t)8 * AC;

    // prologue: issue stages 0..3
    #pragma unroll
    for (int s = 0; s < RING; s++) {
        cp8(dstA + (unsigned)(s & 3) * 4096u, srcA + (size_t)s * sstep, csz);
        cp8(dstW + (unsigned)(s & 3) * 4096u, srcW + (size_t)s * sstep, csz);
        cpcommit();
    }

    // misc loads (overlap the pipeline ramp)
    if (t < 128)       wq[t] = ((const float*)g_wq[b])[t];
    else if (t < 256)  wk[t - 128] = ((const float*)g_wk[b])[t - 128];
    else {
        int n  = (t - 256) >> 7;
        int cc = (t - 256) & 127;
        int m = c0 + cc + 1;
        if (lastcb && cc == 126) m = 0;
        else if (lastcb && cc == 127) m = MC - 1;
        aA[n * 128 + cc] = g_A[n][m];
        aP[n * 128 + cc] = g_P[n][m];
        aR[n * 128 + cc] = g_R[n][m];
    }
    if (lastcb) {
        if (t < 192)                 us[t] = user[b * LROWS + t];
        else if (t < 384)            it[t - 192] = item[b * LROWS + (t - 192)];
    }

    float hq0 = 0.f, hq1 = 0.f, hk0 = 0.f, hk1 = 0.f;

    #pragma unroll
    for (int s = 0; s < NSTG; s++) {
        cpwait(23 - s < 3 ? 23 - s : 3);
        __syncthreads();

        if (s == 16) {
            // causal from hqk partials (parts 0..3)
            if (t < 256) {
                int n = t >> 7, cc = t & 127;
                float4 a0 = hqk[cc], a1 = hqk[128 + cc], a2 = hqk[256 + cc], a3 = hqk[384 + cc];
                float hqv = n ? (a0.y + a1.y + a2.y + a3.y) : (a0.x + a1.x + a2.x + a3.x);
                float hkv = n ? (a0.w + a1.w + a2.w + a3.w) : (a0.z + a1.z + a2.z + a3.z);
                float d = hqv * aP[n * 128 + cc] - hkv * aR[n * 128 + cc];
                c_sh[n * 128 + cc] = aA[n * 128 + cc] / (1.0f + expf(-d));
            }
            __syncthreads();
        }

        const float* A = ring_a + (s & 3) * 1024;
        const float* W = ring_w + (s & 3) * 1024;

        if (s < 16) {
            #pragma unroll
            for (int r = 0; r < 2; r++) {
                int row = 2 * p + r;
                int j = s * 8 + row;
                float x;
                if (special) x = fmaxf((c == 126 ? us[j] : it[j]), 0.f);
                else         x = fmaxf(A[row * 128 + c] * W[row * 128 + c], 0.f);
                if (s < 8) { hq0 = fmaf(x, wq[j], hq0); hq1 = fmaf(x, wq[64 + j], hq1); }
                else       { hk0 = fmaf(x, wk[j - 64], hk0); hk1 = fmaf(x, wk[j], hk1); }
            }
            if (s == 15) hqk[p * 128 + c] = make_float4(hq0, hq1, hk0, hk1);
        } else {
            float v0, v1, v2, v3;
            {
                int row = 2 * p;
                int j = s * 8 + row;
                float x;
                if (special) x = fmaxf((c == 126 ? us[j] : it[j]), 0.f);
                else         x = fmaxf(A[row * 128 + c] * W[row * 128 + c], 0.f);
                v0 = x * c_sh[c];
                v1 = x * c_sh[128 + c];
            }
            {
                int row = 2 * p + 1;
                int j = s * 8 + row;
                float x;
                if (special) x = fmaxf((c == 126 ? us[j] : it[j]), 0.f);
                else         x = fmaxf(A[row * 128 + c] * W[row * 128 + c], 0.f);
                v2 = x * c_sh[c];
                v3 = x * c_sh[128 + c];
            }
            #pragma unroll
            for (int off = 16; off; off >>= 1) {
                v0 += __shfl_xor_sync(0xffffffffu, v0, off);
                v1 += __shfl_xor_sync(0xffffffffu, v1, off);
                v2 += __shfl_xor_sync(0xffffffffu, v2, off);
                v3 += __shfl_xor_sync(0xffffffffu, v3, off);
            }
            if ((c & 31) == 0) {
                int cg = c >> 5;
                int jj = (s - 16) * 8 + 2 * p;
                Spart[(cg * 2 + 0) * 64 + jj]     = v0;
                Spart[(cg * 2 + 1) * 64 + jj]     = v1;
                Spart[(cg * 2 + 0) * 64 + jj + 1] = v2;
                Spart[(cg * 2 + 1) * 64 + jj + 1] = v3;
            }
        }
        __syncthreads();

        int ss = s + RING;
        if (ss < NSTG) {
            cp8(dstA + (unsigned)(ss & 3) * 4096u, srcA + (size_t)ss * sstep, csz);
            cp8(dstW + (unsigned)(ss & 3) * 4096u, srcW + (size_t)ss * sstep, csz);
            cpcommit();
        }
    }

    // epilogue: stage W2 rows 128..191 into the drained attr ring, project, accumulate
    ((float4*)ring_a)[t] = ((const float4*)(W2 + 128 * LD))[t];   // 512 x 16B = 8 KB
    __syncthreads();
    if (t < 64) {
        int l = t >> 1, n = t & 1;
        float s = 0.f;
        #pragma unroll
        for (int j = 0; j < 64; j++) {
            float Sv = Spart[n * 64 + j] + Spart[(2 + n) * 64 + j]
                     + Spart[(4 + n) * 64 + j] + Spart[(6 + n) * 64 + j];
            s = fmaf(ring_a[j * LD + l], Sv, s);
        }
        atomicAdd(&out[b * 64 + l * 2 + n], s);
    }
}

extern "C" void kernel_launch(void* const* d_in, const int* in_sizes, int n_in,
                              void* d_out, int out_size) {
    const float* user       = (const float*)d_in[0];
    const float* item       = (const float*)d_in[1];
    const float* attributor = (const float*)d_in[2];
    const float* adj        = (const float*)d_in[3];
    const float* iw         = (const float*)d_in[4];
    const float* W1         = (const float*)d_in[5];
    const float* W2         = (const float*)d_in[6];
    float* out = (float*)d_out;

    prep_kernel<<<48, 128>>>(user, item, W2, adj, iw, out);
    main_kernel<<<dim3(NCB, BATCH), 512>>>(user, item, attributor, W1, W2, out);
}

// round 12
// speedup vs baseline: 1.2424x; 1.2424x over previous
#include <cuda_runtime.h>
#include <math.h>

// Problem constants
#define BATCH 16
#define LROWS 192   // 6*L rows of raw
#define AC    2046  // attributor columns
#define MC    2048  // M = A + 2
#define LD    32    // L (W_2 output dim)
#define TC    32    // column slots per block
#define NCB   64    // c-blocks (64*32 = 2048 slots: 2046 cols + 2 specials)

// Scratch (device globals; no allocation allowed)
__device__ float g_wq[BATCH][2][64];
__device__ float g_wk[BATCH][2][64];
__device__ float g_A[2][MC];           // adj[m][col_n]
__device__ float g_P[2][MC];           // adj[m][col_n] * iw[m][col_n]
__device__ float g_R[2][MC];           // adj[col_n][m] * iw[col_n][m]

// ---------------------------------------------------------------------------
// Kernel 1 (prep): wq/wk folds + adj/iw packing + d_out zeroing.
// ---------------------------------------------------------------------------
__global__ __launch_bounds__(128) void prep_kernel(
    const float* __restrict__ user, const float* __restrict__ item,
    const float* __restrict__ W2,
    const float* __restrict__ adj, const float* __restrict__ iw,
    float* __restrict__ out) {

    int blk = blockIdx.x;
    int t = threadIdx.x;

    if (blk < 32) {
        int b = blk >> 1;
        int n = blk & 1;
        const float* src = (n ? item : user) + b * LROWS;
        __shared__ float W2s[128 * 33];
        __shared__ float xr[128];
        __shared__ float qs[32];
        __shared__ float ks[32];

        xr[t] = fmaxf(src[t], 0.0f);
        #pragma unroll
        for (int i = 0; i < 32; i++) {
            int idx = t + i * 128;
            W2s[(idx >> 5) * 33 + (idx & 31)] = W2[idx];
        }
        __syncthreads();

        if (t < 32) {
            float s = 0.0f;
            #pragma unroll
            for (int j = 0; j < 64; j++) s = fmaf(xr[j], W2s[j * 33 + t], s);
            qs[t] = s;
        } else if (t < 64) {
            int l = t - 32;
            float s = 0.0f;
            #pragma unroll
            for (int j = 0; j < 64; j++) s = fmaf(xr[64 + j], W2s[(64 + j) * 33 + l], s);
            ks[l] = s;
        }
        __syncthreads();
        if (t < 64) {
            float swq = 0.0f, swk = 0.0f;
            #pragma unroll
            for (int l = 0; l < 32; l++) {
                swq = fmaf(W2s[t * 33 + l],        ks[l], swq);
                swk = fmaf(W2s[(64 + t) * 33 + l], qs[l], swk);
            }
            g_wq[b][n][t] = swq;
            g_wk[b][n][t] = swk;
        }
    } else {
        if (blk == 32) {
            float4 z = make_float4(0.f, 0.f, 0.f, 0.f);
            ((float4*)out)[t]       = z;
            ((float4*)out)[t + 128] = z;
        }
        int m = (blk - 32) * 128 + t;
        size_t row = (size_t)m * MC;
        float a0 = adj[row];
        float a1 = adj[row + (MC - 1)];
        g_A[0][m] = a0;
        g_A[1][m] = a1;
        g_P[0][m] = a0 * iw[row];
        g_P[1][m] = a1 * iw[row + (MC - 1)];
        g_R[0][m] = adj[m] * iw[m];
        size_t lastrow = (size_t)(MC - 1) * MC + m;
        g_R[1][m] = adj[lastrow] * iw[lastrow];
    }
}

// ---------------------------------------------------------------------------
// Kernel 2 (main): grid (cb=64, b=16) = 1024 blocks, 384 threads.
// __launch_bounds__(384, 2): 85 regs available -> the 16-float2 load batch
// (32 dest regs) can be fully in flight. This is the ONLY change vs R9.
// ---------------------------------------------------------------------------
__global__ __launch_bounds__(384, 2) void main_kernel(
    const float* __restrict__ user, const float* __restrict__ item,
    const float* __restrict__ attributor, const float* __restrict__ W1,
    const float* __restrict__ W2, float* __restrict__ out) {

    __shared__ float Vsh[64][TC + 1];
    __shared__ float hq_p[8][2][TC];   // [jq][n][slot]
    __shared__ float hk_p[8][2][TC];
    __shared__ float c_sh[2][TC];
    __shared__ float wq_sh[2][64];
    __shared__ float wk_sh[2][64];
    __shared__ float W2e[64][LD];      // W2 rows 128..191
    __shared__ float Ssh_p[2][2][64];  // [mm-half][n][j]

    int b  = blockIdx.y;
    int cb = blockIdx.x;
    int t  = threadIdx.x;
    int group = t >> 7;          // 0,1,2
    int sub   = t & 127;
    int jq    = sub >> 4;        // 0..7 (8 rows each)
    int lane  = sub & 15;        // 0..15 (2 cols each)
    int c     = cb * TC + lane * 2;

    if (t < 128) {
        ((float*)wq_sh)[t] = ((const float*)g_wq[b])[t];
        ((float*)wk_sh)[t] = ((const float*)g_wk[b])[t];
    } else {
        int r = t - 128;                       // 0..255, 8 floats each
        ((float4*)W2e)[r]       = ((const float4*)(W2 + 128 * LD))[r];
        ((float4*)W2e)[r + 256] = ((const float4*)(W2 + 128 * LD))[r + 256];
    }
    __syncthreads();

    bool lastcb  = (cb == NCB - 1);
    bool special = lastcb && (lane == 15);   // slot pair = (user, item)
    int row0 = group * 64 + jq * 8;          // global raw row of this thread's 8 rows
    int jj0  = jq * 8;                       // row index within the 64-row group

    if (group < 2) {
        const float (*wsel)[64] = (group == 0) ? wq_sh : wk_sh;
        float hA0 = 0.f, hA1 = 0.f, hB0 = 0.f, hB1 = 0.f;
        if (special) {
            const float* uu = user + b * LROWS + row0;
            const float* ii = item + b * LROWS + row0;
            float uv[8], iv[8];
            #pragma unroll
            for (int r = 0; r < 8; r++) uv[r] = uu[r];
            #pragma unroll
            for (int r = 0; r < 8; r++) iv[r] = ii[r];
            #pragma unroll
            for (int r = 0; r < 8; r++) {
                float xu = fmaxf(uv[r], 0.0f);
                float xi = fmaxf(iv[r], 0.0f);
                hA0 = fmaf(xu, wsel[0][jj0 + r], hA0);
                hA1 = fmaf(xu, wsel[1][jj0 + r], hA1);
                hB0 = fmaf(xi, wsel[0][jj0 + r], hB0);
                hB1 = fmaf(xi, wsel[1][jj0 + r], hB1);
            }
        } else {
            const float* ap = attributor + ((size_t)b * LROWS + row0) * AC + c;
            const float* wp = W1 + (size_t)row0 * AC + c;
            float2 av[8], wv[8];
            #pragma unroll
            for (int r = 0; r < 8; r++) av[r] = *(const float2*)(ap + (size_t)r * AC);
            #pragma unroll
            for (int r = 0; r < 8; r++) wv[r] = *(const float2*)(wp + (size_t)r * AC);
            #pragma unroll
            for (int r = 0; r < 8; r++) {
                float x0 = fmaxf(av[r].x * wv[r].x, 0.0f);
                float x1 = fmaxf(av[r].y * wv[r].y, 0.0f);
                hA0 = fmaf(x0, wsel[0][jj0 + r], hA0);
                hA1 = fmaf(x0, wsel[1][jj0 + r], hA1);
                hB0 = fmaf(x1, wsel[0][jj0 + r], hB0);
                hB1 = fmaf(x1, wsel[1][jj0 + r], hB1);
            }
        }
        if (group == 0) {
            hq_p[jq][0][2 * lane] = hA0;      hq_p[jq][1][2 * lane] = hA1;
            hq_p[jq][0][2 * lane + 1] = hB0;  hq_p[jq][1][2 * lane + 1] = hB1;
        } else {
            hk_p[jq][0][2 * lane] = hA0;      hk_p[jq][1][2 * lane] = hA1;
            hk_p[jq][0][2 * lane + 1] = hB0;  hk_p[jq][1][2 * lane + 1] = hB1;
        }
    } else {
        if (special) {
            const float* uu = user + b * LROWS + 128 + jq * 8;
            const float* ii = item + b * LROWS + 128 + jq * 8;
            #pragma unroll
            for (int r = 0; r < 8; r++) {
                Vsh[jj0 + r][30] = fmaxf(uu[r], 0.0f);
                Vsh[jj0 + r][31] = fmaxf(ii[r], 0.0f);
            }
        } else {
            const float* ap = attributor + ((size_t)b * LROWS + 128 + jq * 8) * AC + c;
            const float* wp = W1 + (size_t)(128 + jq * 8) * AC + c;
            float2 av[8], wv[8];
            #pragma unroll
            for (int r = 0; r < 8; r++) av[r] = *(const float2*)(ap + (size_t)r * AC);
            #pragma unroll
            for (int r = 0; r < 8; r++) wv[r] = *(const float2*)(wp + (size_t)r * AC);
            #pragma unroll
            for (int r = 0; r < 8; r++) {
                Vsh[jj0 + r][2 * lane]     = fmaxf(av[r].x * wv[r].x, 0.0f);
                Vsh[jj0 + r][2 * lane + 1] = fmaxf(av[r].y * wv[r].y, 0.0f);
            }
        }
    }
    __syncthreads();

    // causal[b, m, col_n] = sigmoid(h[m,n] - h[n,m]) * adj[m, col_n]
    if (t < 64) {
        int n  = t >> 5;
        int mm = t & (TC - 1);
        int m = cb * TC + mm + 1;
        if (lastcb && mm == 30) m = 0;
        else if (lastcb && mm == 31) m = MC - 1;
        float hq = 0.f, hk = 0.f;
        #pragma unroll
        for (int q = 0; q < 8; q++) { hq += hq_p[q][n][mm]; hk += hk_p[q][n][mm]; }
        float d = hq * g_P[n][m] - hk * g_R[n][m];
        c_sh[n][mm] = g_A[n][m] / (1.0f + expf(-d));
    }
    __syncthreads();

    // partial S: [mh][n][j], each thread sums 16 mm slots (256 threads)
    if (t < 256) {
        int mh = t >> 7;
        int n  = (t >> 6) & 1;
        int j  = t & 63;
        int m0 = mh * 16;
        float s = 0.0f;
        #pragma unroll
        for (int mm = 0; mm < 16; mm++)
            s = fmaf(Vsh[j][m0 + mm], c_sh[n][m0 + mm], s);
        Ssh_p[mh][n][j] = s;
    }
    __syncthreads();

    // fused projection: out[b,l,n] += sum_j W2e[j][l] * S[n][j]
    if (t < 64) {
        int l = t >> 1;
        int n = t & 1;
        float s = 0.0f;
        #pragma unroll
        for (int j = 0; j < 64; j++)
            s = fmaf(W2e[j][l], Ssh_p[0][n][j] + Ssh_p[1][n][j], s);
        atomicAdd(&out[b * 64 + l * 2 + n], s);
    }
}

extern "C" void kernel_launch(void* const* d_in, const int* in_sizes, int n_in,
                              void* d_out, int out_size) {
    const float* user       = (const float*)d_in[0];
    const float* item       = (const float*)d_in[1];
    const float* attributor = (const float*)d_in[2];
    const float* adj        = (const float*)d_in[3];
    const float* iw         = (const float*)d_in[4];
    const float* W1         = (const float*)d_in[5];
    const float* W2         = (const float*)d_in[6];
    float* out = (float*)d_out;

    prep_kernel<<<48, 128>>>(user, item, W2, adj, iw, out);
    main_kernel<<<dim3(NCB, BATCH), 384>>>(user, item, attributor, W1, W2, out);
}

// round 13
// speedup vs baseline: 1.6078x; 1.2941x over previous
#include <cuda_runtime.h>
#include <math.h>

// Problem constants
#define BATCH 16
#define LROWS 192   // 6*L rows of raw
#define AC    2046  // attributor columns
#define MC    2048  // M = A + 2
#define LD    32    // L (W_2 output dim)
#define TCOL  256   // column slots per block
#define NCB   8     // col-blocks (8*256 = 2048 slots: 2046 cols + 2 specials)

// Scratch (device globals; no allocation allowed)
__device__ float g_wq[BATCH][2][64];
__device__ float g_wk[BATCH][2][64];
__device__ float g_A[2][MC];           // adj[m][col_n]
__device__ float g_P[2][MC];           // adj[m][col_n] * iw[m][col_n]
__device__ float g_R[2][MC];           // adj[col_n][m] * iw[col_n][m]

// ---------------------------------------------------------------------------
// Kernel 1 (prep): wq/wk folds + adj/iw packing + d_out zeroing. (unchanged)
// ---------------------------------------------------------------------------
__global__ __launch_bounds__(128) void prep_kernel(
    const float* __restrict__ user, const float* __restrict__ item,
    const float* __restrict__ W2,
    const float* __restrict__ adj, const float* __restrict__ iw,
    float* __restrict__ out) {

    int blk = blockIdx.x;
    int t = threadIdx.x;

    if (blk < 32) {
        int b = blk >> 1;
        int n = blk & 1;
        const float* src = (n ? item : user) + b * LROWS;
        __shared__ float W2s[128 * 33];
        __shared__ float xr[128];
        __shared__ float qs[32];
        __shared__ float ks[32];

        xr[t] = fmaxf(src[t], 0.0f);
        #pragma unroll
        for (int i = 0; i < 32; i++) {
            int idx = t + i * 128;
            W2s[(idx >> 5) * 33 + (idx & 31)] = W2[idx];
        }
        __syncthreads();

        if (t < 32) {
            float s = 0.0f;
            #pragma unroll
            for (int j = 0; j < 64; j++) s = fmaf(xr[j], W2s[j * 33 + t], s);
            qs[t] = s;
        } else if (t < 64) {
            int l = t - 32;
            float s = 0.0f;
            #pragma unroll
            for (int j = 0; j < 64; j++) s = fmaf(xr[64 + j], W2s[(64 + j) * 33 + l], s);
            ks[l] = s;
        }
        __syncthreads();
        if (t < 64) {
            float swq = 0.0f, swk = 0.0f;
            #pragma unroll
            for (int l = 0; l < 32; l++) {
                swq = fmaf(W2s[t * 33 + l],        ks[l], swq);
                swk = fmaf(W2s[(64 + t) * 33 + l], qs[l], swk);
            }
            g_wq[b][n][t] = swq;
            g_wk[b][n][t] = swk;
        }
    } else {
        if (blk == 32) {
            float4 z = make_float4(0.f, 0.f, 0.f, 0.f);
            ((float4*)out)[t]       = z;
            ((float4*)out)[t + 128] = z;
        }
        int m = (blk - 32) * 128 + t;
        size_t row = (size_t)m * MC;
        float a0 = adj[row];
        float a1 = adj[row + (MC - 1)];
        g_A[0][m] = a0;
        g_A[1][m] = a1;
        g_P[0][m] = a0 * iw[row];
        g_P[1][m] = a1 * iw[row + (MC - 1)];
        g_R[0][m] = adj[m] * iw[m];
        size_t lastrow = (size_t)(MC - 1) * MC + m;
        g_R[1][m] = adj[lastrow] * iw[lastrow];
    }
}

// ---------------------------------------------------------------------------
// Kernel 2 (main): row-major streaming for DRAM page locality.
// grid (cb=8, b=16) = 128 blocks x 512 threads (16 warps).
// Warp w<8:  Q rows 8w..8w+7   -> hq partials (smem staged)
// Warp w>=8: K rows 64+8(w-8).. -> hk partials
// causal once, then all warps: V rows 128+4w..+3 folded into S via shfl.
// Per row each warp loads a CONTIGUOUS 1KB span (lane: 4 x float2 at +64-col
// steps) -> per-warp sequential-1KB DRAM bursts instead of 8KB-strided 128B.
// Special nodes: lane31/k3 slot pair of last cb = (user, item) columns.
// ---------------------------------------------------------------------------
__global__ __launch_bounds__(512) void main_kernel(
    const float* __restrict__ user, const float* __restrict__ item,
    const float* __restrict__ attributor, const float* __restrict__ W1,
    const float* __restrict__ W2, float* __restrict__ out) {

    __shared__ __align__(16) float hpool[8 * 2 * TCOL];  // Q partials [w][n][c]
    __shared__ __align__(16) float kpool[8 * 2 * TCOL];  // K partials; W2e aliases after causal
    __shared__ float c_sh[2][TCOL];
    __shared__ float aA[2][TCOL], aP[2][TCOL], aR[2][TCOL];
    __shared__ float wqs[128], wks[128];   // [n*64+j]
    __shared__ float us[LROWS], its[LROWS];
    __shared__ float Ssh[2][64];

    int b  = blockIdx.y;
    int cb = blockIdx.x;
    int t  = threadIdx.x;
    int w  = t >> 5;
    int l  = t & 31;
    int c0 = cb * TCOL;
    bool lastcb = (cb == NCB - 1);

    // prologue loads
    if (t < 128)       wqs[t]       = ((const float*)g_wq[b])[t];
    else if (t < 256)  wks[t - 128] = ((const float*)g_wk[b])[t - 128];
    {
        int n = t >> 8, c = t & 255;
        int m = c0 + c + 1;
        if (lastcb && c == 254) m = 0;
        else if (lastcb && c == 255) m = MC - 1;
        aA[n][c] = g_A[n][m];
        aP[n][c] = g_P[n][m];
        aR[n][c] = g_R[n][m];
    }
    if (lastcb) {
        if (t < LROWS)          us[t] = user[b * LROWS + t];
        else if (t < 2 * LROWS) its[t - LROWS] = item[b * LROWS + t - LROWS];
    }
    __syncthreads();

    // ---- phase 1: Q/K row streaming with per-warp contiguous-1KB row spans
    {
        int qk = w >> 3;                 // 0: Q warps, 1: K warps
        int wr = w & 7;
        int r0 = qk * 64 + wr * 8;       // first global raw row
        const float* wsel = qk ? wks : wqs;
        float acc[4][4];                 // [k][x0n0, x0n1, x1n0, x1n1]
        #pragma unroll
        for (int k = 0; k < 4; k++)
            acc[k][0] = acc[k][1] = acc[k][2] = acc[k][3] = 0.f;

        #pragma unroll
        for (int itr = 0; itr < 4; itr++) {       // 2 rows per iteration
            int r = r0 + itr * 2;
            float2 av[2][4], wv[2][4];
            #pragma unroll
            for (int rr = 0; rr < 2; rr++) {
                const float* ap = attributor + ((size_t)(b * LROWS + r + rr)) * AC + c0 + 2 * l;
                const float* wp = W1 + ((size_t)(r + rr)) * AC + c0 + 2 * l;
                #pragma unroll
                for (int k = 0; k < 4; k++) {
                    bool sp = lastcb && (l == 31) && (k == 3);
                    av[rr][k] = sp ? make_float2(0.f, 0.f) : *(const float2*)(ap + 64 * k);
                    wv[rr][k] = sp ? make_float2(0.f, 0.f) : *(const float2*)(wp + 64 * k);
                }
            }
            #pragma unroll
            for (int rr = 0; rr < 2; rr++) {
                int rg = r + rr;                 // global raw row
                int j  = wr * 8 + itr * 2 + rr;  // j within group 0..63
                float w0 = wsel[j], w1 = wsel[64 + j];
                #pragma unroll
                for (int k = 0; k < 4; k++) {
                    float x0, x1;
                    if (lastcb && (l == 31) && (k == 3)) {
                        x0 = fmaxf(us[rg], 0.f);     // user node (m=0)
                        x1 = fmaxf(its[rg], 0.f);    // item node (m=2047)
                    } else {
                        x0 = fmaxf(av[rr][k].x * wv[rr][k].x, 0.f);
                        x1 = fmaxf(av[rr][k].y * wv[rr][k].y, 0.f);
                    }
                    acc[k][0] = fmaf(x0, w0, acc[k][0]);
                    acc[k][1] = fmaf(x0, w1, acc[k][1]);
                    acc[k][2] = fmaf(x1, w0, acc[k][2]);
                    acc[k][3] = fmaf(x1, w1, acc[k][3]);
                }
            }
        }
        float* dst = (qk ? kpool : hpool) + wr * (2 * TCOL);
        #pragma unroll
        for (int k = 0; k < 4; k++) {
            int c = 64 * k + 2 * l;
            dst[c]            = acc[k][0];
            dst[TCOL + c]     = acc[k][1];
            dst[c + 1]        = acc[k][2];
            dst[TCOL + c + 1] = acc[k][3];
        }
    }
    __syncthreads();

    // ---- causal: reduce 8 partials each, sigmoid
    {
        int n = t >> 8, c = t & 255;
        float hq = 0.f, hk = 0.f;
        #pragma unroll
        for (int w8 = 0; w8 < 8; w8++) {
            hq += hpool[w8 * (2 * TCOL) + n * TCOL + c];
            hk += kpool[w8 * (2 * TCOL) + n * TCOL + c];
        }
        float d = hq * aP[n][c] - hk * aR[n][c];
        c_sh[n][c] = aA[n][c] / (1.0f + expf(-d));
    }
    __syncthreads();

    // W2e (rows 128..191 of W2) aliases kpool (dead after causal)
    ((float4*)kpool)[t] = ((const float4*)(W2 + 128 * LD))[t];   // 512*4 = 2048 floats

    // ---- V phase: each warp folds its 4 V rows into S via shfl reduce
    {
        int vr0 = 128 + w * 4;
        #pragma unroll
        for (int itr = 0; itr < 2; itr++) {
            int r = vr0 + itr * 2;
            float2 av[2][4], wv[2][4];
            #pragma unroll
            for (int rr = 0; rr < 2; rr++) {
                const float* ap = attributor + ((size_t)(b * LROWS + r + rr)) * AC + c0 + 2 * l;
                const float* wp = W1 + ((size_t)(r + rr)) * AC + c0 + 2 * l;
                #pragma unroll
                for (int k = 0; k < 4; k++) {
                    bool sp = lastcb && (l == 31) && (k == 3);
                    av[rr][k] = sp ? make_float2(0.f, 0.f) : *(const float2*)(ap + 64 * k);
                    wv[rr][k] = sp ? make_float2(0.f, 0.f) : *(const float2*)(wp + 64 * k);
                }
            }
            #pragma unroll
            for (int rr = 0; rr < 2; rr++) {
                int rg = r + rr;
                int j  = rg - 128;
                float v0 = 0.f, v1 = 0.f;
                #pragma unroll
                for (int k = 0; k < 4; k++) {
                    float x0, x1;
                    if (lastcb && (l == 31) && (k == 3)) {
                        x0 = fmaxf(us[rg], 0.f);
                        x1 = fmaxf(its[rg], 0.f);
                    } else {
                        x0 = fmaxf(av[rr][k].x * wv[rr][k].x, 0.f);
                        x1 = fmaxf(av[rr][k].y * wv[rr][k].y, 0.f);
                    }
                    int c = 64 * k + 2 * l;
                    v0 = fmaf(x0, c_sh[0][c], v0);
                    v0 = fmaf(x1, c_sh[0][c + 1], v0);
                    v1 = fmaf(x0, c_sh[1][c], v1);
                    v1 = fmaf(x1, c_sh[1][c + 1], v1);
                }
                #pragma unroll
                for (int off = 16; off; off >>= 1) {
                    v0 += __shfl_xor_sync(0xffffffffu, v0, off);
                    v1 += __shfl_xor_sync(0xffffffffu, v1, off);
                }
                if (l == 0) { Ssh[0][j] = v0; Ssh[1][j] = v1; }
            }
        }
    }
    __syncthreads();

    // ---- fused projection: out[b,l,n] += sum_j W2e[j][l] * S[n][j]
    if (t < 64) {
        int ll = t >> 1;
        int n  = t & 1;
        float s = 0.0f;
        #pragma unroll
        for (int j = 0; j < 64; j++)
            s = fmaf(kpool[j * LD + ll], Ssh[n][j], s);
        atomicAdd(&out[b * 64 + ll * 2 + n], s);
    }
}

extern "C" void kernel_launch(void* const* d_in, const int* in_sizes, int n_in,
                              void* d_out, int out_size) {
    const float* user       = (const float*)d_in[0];
    const float* item       = (const float*)d_in[1];
    const float* attributor = (const float*)d_in[2];
    const float* adj        = (const float*)d_in[3];
    const float* iw         = (const float*)d_in[4];
    const float* W1         = (const float*)d_in[5];
    const float* W2         = (const float*)d_in[6];
    float* out = (float*)d_out;

    prep_kernel<<<48, 128>>>(user, item, W2, adj, iw, out);
    main_kernel<<<dim3(NCB, BATCH), 512>>>(user, item, attributor, W1, W2, out);
}